// round 8
// baseline (speedup 1.0000x reference)
#include <cuda_runtime.h>
#include <cuda_bf16.h>
#include <math.h>
#include <stdint.h>

#define N_VEC   16384
#define K_CODES 8192
#define DDIM    64
#define OUT_ELEMS 1048576            // 16*64*32*32
#define NTILES  64                   // 8192 / 128
#define MARGIN  1e-4f

// ---------------------------------------------------------------------------
// scratch (no cudaMalloc allowed)
__device__ __align__(256) float          g_cn[K_CODES * DDIM];   // normalized codebook fp32
__device__ __align__(256) __nv_bfloat16  g_cbH[K_CODES * DDIM];  // normalized codebook bf16 hi
__device__ __align__(256) __nv_bfloat16  g_cbL[K_CODES * DDIM];  // lo
__device__ __align__(256) __nv_bfloat16  g_zH[N_VEC * DDIM];     // z transposed [n][k] bf16 hi
__device__ __align__(256) __nv_bfloat16  g_zL[N_VEC * DDIM];     // lo
__device__ int    g_idx[N_VEC];
__device__ int    g_bin[K_CODES];
__device__ int    g_flag[N_VEC];
__device__ int    g_nflag;
__device__ double g_lossd;

// ---------------------------------------------------------------------------
__device__ __forceinline__ uint32_t smem_u32(const void* p) {
    uint32_t a;
    asm("{ .reg .u64 t; cvta.to.shared.u64 t, %1; cvt.u32.u64 %0, t; }"
        : "=r"(a) : "l"(p));
    return a;
}
__device__ __forceinline__ void cpa16(uint32_t s, const void* g) {
    asm volatile("cp.async.cg.shared.global [%0], [%1], 16;" :: "r"(s), "l"(g));
}
#define CP_COMMIT() asm volatile("cp.async.commit_group;" ::: "memory")
#define CP_WAIT0()  asm volatile("cp.async.wait_group 0;" ::: "memory")
#define CP_WAIT1()  asm volatile("cp.async.wait_group 1;" ::: "memory")

__device__ __forceinline__ void ldsm4(uint32_t* r, uint32_t addr) {
    asm volatile("ldmatrix.sync.aligned.m8n8.x4.shared.b16 {%0,%1,%2,%3}, [%4];"
                 : "=r"(r[0]), "=r"(r[1]), "=r"(r[2]), "=r"(r[3]) : "r"(addr));
}
__device__ __forceinline__ void mma_bf16(float* c, const uint32_t* a,
                                         uint32_t b0, uint32_t b1) {
    asm volatile("mma.sync.aligned.m16n8k16.row.col.f32.bf16.bf16.f32 "
                 "{%0,%1,%2,%3}, {%4,%5,%6,%7}, {%8,%9}, {%0,%1,%2,%3};"
                 : "+f"(c[0]), "+f"(c[1]), "+f"(c[2]), "+f"(c[3])
                 : "r"(a[0]), "r"(a[1]), "r"(a[2]), "r"(a[3]), "r"(b0), "r"(b1));
}
#define SW(x) ((x) ^ (((x) >> 3) & 0x70))
#define TSTR 132

// ---------------------------------------------------------------------------
// Fused prep: zero counters | normalize+split codebook | transpose+split z
__global__ void prep_kernel(const float* __restrict__ z,
                            const float* __restrict__ embed) {
    int blk = blockIdx.x;
    int t = threadIdx.x;
    if (blk < 32) {
        // ---- zero ----
        int i = blk * 256 + t;
        if (i < K_CODES) g_bin[i] = 0;
        if (i == 0) { g_lossd = 0.0; g_nflag = 0; }
    } else if (blk < 32 + 1024) {
        // ---- norm_split: warp per codebook row ----
        int wid = t >> 5, lane = t & 31;
        int row = (blk - 32) * 8 + wid;
        float a = embed[row * 64 + lane];
        float b = embed[row * 64 + lane + 32];
        float s = a * a + b * b;
#pragma unroll
        for (int off = 16; off >= 1; off >>= 1) s += __shfl_xor_sync(0xFFFFFFFFu, s, off);
        float inv = 1.0f / fmaxf(sqrtf(s), 1e-12f);
        float ca = a * inv, cb = b * inv;
        g_cn[row * 64 + lane] = ca;
        g_cn[row * 64 + lane + 32] = cb;
        __nv_bfloat16 ha = __float2bfloat16(ca), hb = __float2bfloat16(cb);
        g_cbH[row * 64 + lane] = ha;
        g_cbH[row * 64 + lane + 32] = hb;
        g_cbL[row * 64 + lane] = __float2bfloat16(ca - __bfloat162float(ha));
        g_cbL[row * 64 + lane + 32] = __float2bfloat16(cb - __bfloat162float(hb));
    } else {
        // ---- z_split ----
        __shared__ float tile[64 * TSTR];
        int bb = blk - (32 + 1024);
        int b = bb >> 3;
        int hwb = bb & 7;
        const float4* z4 = (const float4*)z;
#pragma unroll
        for (int i = 0; i < 8; i++) {
            int f4 = t + i * 256;
            int k = f4 >> 5, w = f4 & 31;
            *(float4*)&tile[k * TSTR + w * 4] = z4[b * 16384 + k * 256 + hwb * 32 + w];
        }
        __syncthreads();
        int r = t >> 1, half = t & 1;
        int n = b * 1024 + hwb * 128 + r;
        __nv_bfloat162* zh2 = (__nv_bfloat162*)g_zH;
        __nv_bfloat162* zl2 = (__nv_bfloat162*)g_zL;
#pragma unroll
        for (int kk = 0; kk < 16; kk++) {
            int k = half * 32 + kk * 2;
            float v0 = tile[k * TSTR + r];
            float v1 = tile[(k + 1) * TSTR + r];
            __nv_bfloat162 hv = __floats2bfloat162_rn(v0, v1);
            __nv_bfloat162 lv = __floats2bfloat162_rn(v0 - __bfloat162float(hv.x),
                                                      v1 - __bfloat162float(hv.y));
            zh2[(n * 64 + k) >> 1] = hv;
            zl2[(n * 64 + k) >> 1] = lv;
        }
    }
}

// ---------------------------------------------------------------------------
// Main kernel: 512 CTAs x 256 threads, 32 rows/CTA, 8 warps each owning a
// private 16-col slice of every 128-code tile. Warp-private 3-stage cp.async
// ring (4KB/stage) -> ZERO mainloop barriers. 2 CTAs/SM = 4 warps/SMSP.
// Dyn smem: 8 warps * 12KB = 96KB (+pad). A (8KB) transient at dbase.
extern __shared__ char dsm[];
__global__ void __launch_bounds__(256, 2) hmma_argmax_kernel() {
    uint32_t sraw = smem_u32(dsm);
    uint32_t dbase = (sraw + 1023) & ~1023u;
    char* dp = dsm + (int)(dbase - sraw);
    int tid = threadIdx.x, lane = tid & 31, wid = tid >> 5;
    int nbase = blockIdx.x * 32;

    // ---- A prologue: 32 rows of zH/zL into dbase (hi) / dbase+4096 (lo) ----
    {
        const int4* h4 = (const int4*)g_zH;
        const int4* l4 = (const int4*)g_zL;
        int r = tid >> 3, c = tid & 7;      // 256 threads = 256 chunks each array
        uint32_t off = SW((uint32_t)(r * 128 + c * 16));
        cpa16(dbase + off, &h4[(nbase + r) * 8 + c]);
        cpa16(dbase + 4096 + off, &l4[(nbase + r) * 8 + c]);
        CP_COMMIT();
        CP_WAIT0();
        __syncthreads();
    }

    // ---- A fragments in registers (rows 32 = 2 x m16) ----
    uint32_t ah[2][4][4], al[2][4][4];
    {
        int rA = ((lane >> 3) & 1) * 8 + (lane & 7);
        int kA = (lane >> 4) * 16;
#pragma unroll
        for (int mf = 0; mf < 2; mf++)
#pragma unroll
            for (int ks = 0; ks < 4; ks++) {
                uint32_t off = SW((uint32_t)((mf * 16 + rA) * 128 + ks * 32 + kA));
                ldsm4(ah[mf][ks], dbase + off);
                ldsm4(al[mf][ks], dbase + 4096 + off);
            }
    }
    __syncthreads();   // everyone done with A region before warp0 streams over it

    // ---- warp-private streaming setup ----
    uint32_t wbase = dbase + wid * 12288;         // 3 stages x 4KB
    int rl = lane >> 3, cl = lane & 7;
    uint32_t base_rc = (uint32_t)(rl * 128 + cl * 16);
    int src_rc = rl * 8 + cl;                     // int4 units
    uint32_t rowB = (uint32_t)((((lane >> 4) & 1) * 8 + (lane & 7)) * 128
                               + ((lane >> 3) & 1) * 16);
    const int4* cbh4 = (const int4*)g_cbH;
    const int4* cbl4 = (const int4*)g_cbL;

    auto prefetch = [&](int nt) {
        uint32_t st = wbase + (nt % 3) * 4096;
        int srcb = (nt * 128 + wid * 16) * 8 + src_rc;
#pragma unroll
        for (int q = 0; q < 4; q++) {
            uint32_t x = base_rc + q * 512;
            uint32_t off = x ^ ((x >> 3) & 0x70);
            cpa16(st + off, &cbh4[srcb + q * 32]);
            cpa16(st + 2048 + off, &cbl4[srcb + q * 32]);
        }
        CP_COMMIT();
    };

    prefetch(0);
    prefetch(1);

    float g1[4], g2[4];
    int gi[4];
#pragma unroll
    for (int s = 0; s < 4; s++) { g1[s] = -1e30f; g2[s] = -1e30f; gi[s] = 0; }

    for (int nt = 0; nt < NTILES; nt++) {
        if (nt < NTILES - 1) CP_WAIT1(); else CP_WAIT0();
        if (nt < NTILES - 2) prefetch(nt + 2);
        uint32_t st = wbase + (nt % 3) * 4096;

        float C[2][2][4];
#pragma unroll
        for (int mf = 0; mf < 2; mf++)
#pragma unroll
            for (int j = 0; j < 2; j++)
#pragma unroll
                for (int q = 0; q < 4; q++) C[mf][j][q] = 0.0f;

#pragma unroll
        for (int ks = 0; ks < 4; ks++) {
            uint32_t x = rowB + ks * 32;
            uint32_t off = x ^ ((x >> 3) & 0x70);
            uint32_t bh[4], bl[4];
            ldsm4(bh, st + off);
            ldsm4(bl, st + 2048 + off);
#pragma unroll
            for (int mf = 0; mf < 2; mf++) {
                mma_bf16(C[mf][0], ah[mf][ks], bh[0], bh[1]);
                mma_bf16(C[mf][1], ah[mf][ks], bh[2], bh[3]);
            }
#pragma unroll
            for (int mf = 0; mf < 2; mf++) {
                mma_bf16(C[mf][0], al[mf][ks], bh[0], bh[1]);
                mma_bf16(C[mf][1], al[mf][ks], bh[2], bh[3]);
            }
#pragma unroll
            for (int mf = 0; mf < 2; mf++) {
                mma_bf16(C[mf][0], ah[mf][ks], bl[0], bl[1]);
                mma_bf16(C[mf][1], ah[mf][ks], bl[2], bl[3]);
            }
        }

        // ---- running top-2 argmax update (4 s-slots; 4 values each) ----
        int cb = nt * 128 + wid * 16 + (lane & 3) * 2;
#pragma unroll
        for (int mf = 0; mf < 2; mf++)
#pragma unroll
            for (int h = 0; h < 2; h++) {
                int s = mf * 2 + h;
                float v00 = C[mf][0][2 * h], v01 = C[mf][0][2 * h + 1];
                float v10 = C[mf][1][2 * h], v11 = C[mf][1][2 * h + 1];
                float tm = fmaxf(fmaxf(v00, v01), fmaxf(v10, v11));
                if (tm > g1[s]) {
                    float m1 = -1e30f, m2 = -1e30f;
                    int mi = 0;
                    // ascending col order: cb, cb+1, cb+8, cb+9
                    if (v00 > m1) { m2 = m1; m1 = v00; mi = cb; }
                    else if (v00 > m2) m2 = v00;
                    if (v01 > m1) { m2 = m1; m1 = v01; mi = cb + 1; }
                    else if (v01 > m2) m2 = v01;
                    if (v10 > m1) { m2 = m1; m1 = v10; mi = cb + 8; }
                    else if (v10 > m2) m2 = v10;
                    if (v11 > m1) { m2 = m1; m1 = v11; mi = cb + 9; }
                    else if (v11 > m2) m2 = v11;
                    g2[s] = fmaxf(g1[s], m2);
                    g1[s] = m1;
                    gi[s] = mi;
                } else {
                    g2[s] = fmaxf(g2[s], tm);
                }
            }
    }

    // ---- quad reduce (lanes lane^1, lane^2 share rows, differ in cols) ----
#pragma unroll
    for (int s = 0; s < 4; s++) {
#pragma unroll
        for (int d = 1; d <= 2; d <<= 1) {
            float ov1 = __shfl_xor_sync(0xFFFFFFFFu, g1[s], d);
            float ov2 = __shfl_xor_sync(0xFFFFFFFFu, g2[s], d);
            int   oi  = __shfl_xor_sync(0xFFFFFFFFu, gi[s], d);
            if (ov1 > g1[s]) { g2[s] = fmaxf(g1[s], ov2); g1[s] = ov1; gi[s] = oi; }
            else {
                if (ov1 == g1[s] && oi < gi[s]) gi[s] = oi;
                g2[s] = fmaxf(g2[s], ov1);
            }
        }
    }

    // ---- cross-warp (8-way) merge via smem ----
    __syncthreads();                  // all warps done streaming; reuse dbase
    float* rv1 = (float*)dp;          // [8][32]
    float* rv2 = rv1 + 256;           // [8][32]
    int*   ri  = (int*)(rv2 + 256);   // [8][32]
    if ((lane & 3) == 0) {
#pragma unroll
        for (int s = 0; s < 4; s++) {
            int mf = s >> 1, h = s & 1;
            int row = mf * 16 + h * 8 + (lane >> 2);
            rv1[wid * 32 + row] = g1[s];
            rv2[wid * 32 + row] = g2[s];
            ri[wid * 32 + row]  = gi[s];
        }
    }
    __syncthreads();
    if (tid < 32) {
        float v1 = rv1[tid], v2 = rv2[tid];
        int i1 = ri[tid];
#pragma unroll
        for (int w = 1; w < 8; w++) {
            float ov1 = rv1[w * 32 + tid], ov2 = rv2[w * 32 + tid];
            int   oi  = ri[w * 32 + tid];
            if (ov1 > v1) { v2 = fmaxf(v1, ov2); v1 = ov1; i1 = oi; }
            else {
                if (ov1 == v1 && oi < i1) i1 = oi;
                v2 = fmaxf(v2, fmaxf(ov1, -1e30f));
                v2 = fmaxf(v2, ov2 > ov1 ? ov1 : ov2);  // conservative: ov1 <= v1 anyway
            }
        }
        g_idx[nbase + tid] = i1;
        if (v1 - v2 < MARGIN) {
            int slot = atomicAdd(&g_nflag, 1);
            g_flag[slot] = nbase + tid;
        }
    }
}

// ---------------------------------------------------------------------------
// Exact fp32 rescore of flagged rows. warp per row.
__global__ void rescore_kernel(const float* __restrict__ z) {
    __shared__ float zrow[8][64];
    int wid = threadIdx.x >> 5, lane = threadIdx.x & 31;
    int gw = blockIdx.x * 8 + wid;
    int nf = g_nflag;
    for (int f = gw; f < nf; f += 64 * 8) {
        int n = g_flag[f];
        int b = n >> 10, hw = n & 1023;
        zrow[wid][lane]      = z[b * 65536 + lane * 1024 + hw];
        zrow[wid][lane + 32] = z[b * 65536 + (lane + 32) * 1024 + hw];
        __syncwarp();
        float v1 = -1e30f; int i1 = 0;
        for (int j = lane; j < K_CODES; j += 32) {
            const float4* cr = (const float4*)(g_cn + j * 64);
            float s = 0.0f;
#pragma unroll
            for (int q = 0; q < 16; q++) {
                float4 cv = cr[q];
                s += cv.x * zrow[wid][q * 4 + 0];
                s += cv.y * zrow[wid][q * 4 + 1];
                s += cv.z * zrow[wid][q * 4 + 2];
                s += cv.w * zrow[wid][q * 4 + 3];
            }
            if (s > v1) { v1 = s; i1 = j; }
        }
#pragma unroll
        for (int off = 16; off >= 1; off >>= 1) {
            float ov = __shfl_xor_sync(0xFFFFFFFFu, v1, off);
            int   oi = __shfl_xor_sync(0xFFFFFFFFu, i1, off);
            if (ov > v1 || (ov == v1 && oi < i1)) { v1 = ov; i1 = oi; }
        }
        if (lane == 0) g_idx[n] = i1;
        __syncwarp();
    }
}

// ---------------------------------------------------------------------------
// Gather + bincount + loss.
__global__ void gather_kernel(const float* __restrict__ z,
                              const float* __restrict__ embed,
                              float* __restrict__ out) {
    __shared__ float qt[64 * TSTR];
    int t = threadIdx.x;
    int nbase = blockIdx.x * 128;
    int b = nbase >> 10, hw0 = nbase & 1023;

    {
        int r = t >> 1, half = t & 1;
        int idx = g_idx[nbase + r];
        if (half == 0) atomicAdd(&g_bin[idx], 1);
        const float4* er = (const float4*)(embed + idx * 64 + half * 32);
#pragma unroll
        for (int q = 0; q < 8; q++) {
            float4 v = er[q];
            int k = half * 32 + q * 4;
            qt[(k + 0) * TSTR + r] = v.x;
            qt[(k + 1) * TSTR + r] = v.y;
            qt[(k + 2) * TSTR + r] = v.z;
            qt[(k + 3) * TSTR + r] = v.w;
        }
    }
    __syncthreads();

    float s = 0.0f;
#pragma unroll
    for (int i = 0; i < 8; i++) {
        int f4 = t + i * 256;
        int k = f4 >> 5, hw4 = (f4 & 31) * 4;
        float4 qv = *(float4*)&qt[k * TSTR + hw4];
        int off = b * 65536 + k * 1024 + hw0 + hw4;
        float4 zv = *(const float4*)&z[off];
        *(float4*)&out[off] = qv;
        float d0 = qv.x - zv.x, d1 = qv.y - zv.y, d2 = qv.z - zv.z, d3 = qv.w - zv.w;
        s += d0 * d0 + d1 * d1 + d2 * d2 + d3 * d3;
    }
#pragma unroll
    for (int off = 16; off >= 1; off >>= 1) s += __shfl_xor_sync(0xFFFFFFFFu, s, off);
    __shared__ float red[8];
    int lane = t & 31, wid = t >> 5;
    if (lane == 0) red[wid] = s;
    __syncthreads();
    if (wid == 0) {
        s = (lane < 8) ? red[lane] : 0.0f;
#pragma unroll
        for (int off = 4; off >= 1; off >>= 1) s += __shfl_xor_sync(0xFFFFFFFFu, s, off);
        if (lane == 0) atomicAdd(&g_lossd, (double)s);
    }
}

// ---------------------------------------------------------------------------
__global__ void finalize_kernel(float* __restrict__ out) {
    int t = blockIdx.x * blockDim.x + threadIdx.x;
    if (t == 0)
        out[OUT_ELEMS] = (float)(1.25 * g_lossd * (1.0 / (double)OUT_ELEMS));
    if (t < N_VEC)
        out[OUT_ELEMS + 1 + t] = (float)g_idx[t];
    if (t < K_CODES)
        out[OUT_ELEMS + 1 + N_VEC + t] = (float)g_bin[t];
}

// ---------------------------------------------------------------------------
extern "C" void kernel_launch(void* const* d_in, const int* in_sizes, int n_in,
                              void* d_out, int out_size) {
    const float* z     = (const float*)d_in[0];       // [16,64,32,32]
    const float* embed = (const float*)d_in[1];       // [8192,64]
    float* out = (float*)d_out;

    cudaFuncSetAttribute(hmma_argmax_kernel,
                         cudaFuncAttributeMaxDynamicSharedMemorySize, 99328);

    prep_kernel<<<32 + 1024 + 128, 256>>>(z, embed);
    hmma_argmax_kernel<<<512, 256, 99328>>>();
    rescore_kernel<<<64, 256>>>(z);
    gather_kernel<<<128, 256>>>(z, embed, out);
    finalize_kernel<<<96, 256>>>(out);
}

// round 9
// speedup vs baseline: 1.1392x; 1.1392x over previous
#include <cuda_runtime.h>
#include <cuda_bf16.h>
#include <math.h>
#include <stdint.h>

#define N_VEC   16384
#define K_CODES 8192
#define DDIM    64
#define OUT_ELEMS 1048576            // 16*64*32*32
#define NTILES  64                   // 8192 / 128
#define SZ      6000.0f
#define SC      30000.0f
#define W_FIX   360000.0f            // 2e-3 * SZ * SC

// ---------------------------------------------------------------------------
// scratch (no cudaMalloc allowed)
__device__ __align__(256) float   g_cn[K_CODES * DDIM];   // normalized codebook fp32
__device__ __align__(256) int8_t  g_cq[K_CODES * 128];    // [lc(64) | hc(64)] per code
__device__ __align__(256) int8_t  g_zq[N_VEC * 128];      // [hz(64) | lz(64)] per row
__device__ int    g_idx[N_VEC];
__device__ int    g_bin[K_CODES];
__device__ int    g_flagF[N_VEC];     // full-rescan rows
__device__ int    g_f2n[N_VEC];       // 2-candidate rows
__device__ int    g_f2j[N_VEC];       // their 2nd candidate index
__device__ int    g_nflagF;
__device__ int    g_nflag2;
__device__ double g_lossd;

// ---------------------------------------------------------------------------
__device__ __forceinline__ uint32_t smem_u32(const void* p) {
    uint32_t a;
    asm("{ .reg .u64 t; cvta.to.shared.u64 t, %1; cvt.u32.u64 %0, t; }"
        : "=r"(a) : "l"(p));
    return a;
}
__device__ __forceinline__ void cpa16(uint32_t s, const void* g) {
    asm volatile("cp.async.cg.shared.global [%0], [%1], 16;" :: "r"(s), "l"(g));
}
#define CP_COMMIT() asm volatile("cp.async.commit_group;" ::: "memory")
#define CP_WAIT0()  asm volatile("cp.async.wait_group 0;" ::: "memory")
#define CP_WAIT1()  asm volatile("cp.async.wait_group 1;" ::: "memory")

__device__ __forceinline__ void ldsm4(uint32_t* r, uint32_t addr) {
    asm volatile("ldmatrix.sync.aligned.m8n8.x4.shared.b16 {%0,%1,%2,%3}, [%4];"
                 : "=r"(r[0]), "=r"(r[1]), "=r"(r[2]), "=r"(r[3]) : "r"(addr));
}
__device__ __forceinline__ void mma_s8(int* c, const uint32_t* a,
                                       uint32_t b0, uint32_t b1) {
    asm volatile("mma.sync.aligned.m16n8k32.row.col.s32.s8.s8.s32 "
                 "{%0,%1,%2,%3}, {%4,%5,%6,%7}, {%8,%9}, {%0,%1,%2,%3};"
                 : "+r"(c[0]), "+r"(c[1]), "+r"(c[2]), "+r"(c[3])
                 : "r"(a[0]), "r"(a[1]), "r"(a[2]), "r"(a[3]), "r"(b0), "r"(b1));
}
#define SW(x) ((x) ^ (((x) >> 3) & 0x70))
#define TSTR 132

// exact merge of two top-3 candidate sets (values + top-2 indices)
__device__ __forceinline__ void top3_merge(float& v1, int& i1, float& v2, int& i2,
                                           float& v3, float b1, int bi1, float b2,
                                           int bi2, float b3) {
    bool bw = (b1 > v1) || (b1 == v1 && bi1 < i1);
    float x, y2, c2v, c3; int xi, c2i;
    if (bw) { x = v1; xi = i1; y2 = v2; c2v = b2; c2i = bi2; c3 = b3; v1 = b1; i1 = bi1; }
    else    { x = b1; xi = bi1; y2 = b2; c2v = v2; c2i = i2; c3 = v3; }
    if (x > c2v || (x == c2v && xi < c2i)) { v2 = x; i2 = xi; v3 = fmaxf(y2, c2v); }
    else                                   { v2 = c2v; i2 = c2i; v3 = fmaxf(x, c3); }
}

// ---------------------------------------------------------------------------
// Fused prep: zero counters | normalize+quantize codebook | transpose+quantize z
__global__ void prep_kernel(const float* __restrict__ z,
                            const float* __restrict__ embed) {
    int blk = blockIdx.x;
    int t = threadIdx.x;
    if (blk < 32) {
        int i = blk * 256 + t;
        if (i < K_CODES) g_bin[i] = 0;
        if (i == 0) { g_lossd = 0.0; g_nflagF = 0; g_nflag2 = 0; }
    } else if (blk < 32 + 1024) {
        // ---- codebook: normalize -> fp32 + int8 split [lc | hc] ----
        int wid = t >> 5, lane = t & 31;
        int row = (blk - 32) * 8 + wid;
        float a = embed[row * 64 + lane];
        float b = embed[row * 64 + lane + 32];
        float s = a * a + b * b;
#pragma unroll
        for (int off = 16; off >= 1; off >>= 1) s += __shfl_xor_sync(0xFFFFFFFFu, s, off);
        float inv = 1.0f / fmaxf(sqrtf(s), 1e-12f);
        float ca = a * inv, cb = b * inv;
        g_cn[row * 64 + lane] = ca;
        g_cn[row * 64 + lane + 32] = cb;
        int c16a = __float2int_rn(ca * SC);
        int c16b = __float2int_rn(cb * SC);
        int ha = (c16a + 128) >> 8, hb = (c16b + 128) >> 8;
        int la = c16a - (ha << 8),  lb = c16b - (hb << 8);
        g_cq[row * 128 + lane]           = (int8_t)la;
        g_cq[row * 128 + lane + 32]      = (int8_t)lb;
        g_cq[row * 128 + 64 + lane]      = (int8_t)ha;
        g_cq[row * 128 + 64 + lane + 32] = (int8_t)hb;
    } else {
        // ---- z: transpose -> int8 split [hz | lz] ----
        __shared__ float tile[64 * TSTR];
        int bb = blk - (32 + 1024);
        int b = bb >> 3;
        int hwb = bb & 7;
        const float4* z4 = (const float4*)z;
#pragma unroll
        for (int i = 0; i < 8; i++) {
            int f4 = t + i * 256;
            int k = f4 >> 5, w = f4 & 31;
            *(float4*)&tile[k * TSTR + w * 4] = z4[b * 16384 + k * 256 + hwb * 32 + w];
        }
        __syncthreads();
        int r = t >> 1, half = t & 1;
        int n = b * 1024 + hwb * 128 + r;
        uint32_t hw_[8], lw_[8];
#pragma unroll
        for (int q = 0; q < 8; q++) {
            uint32_t hb4 = 0, lb4 = 0;
#pragma unroll
            for (int e = 0; e < 4; e++) {
                int k = half * 32 + q * 4 + e;
                float v = tile[k * TSTR + r];
                int z16 = __float2int_rn(fminf(fmaxf(v * SZ, -32639.0f), 32639.0f));
                int h = (z16 + 128) >> 8;
                int l = z16 - (h << 8);
                hb4 |= ((uint32_t)(uint8_t)(int8_t)h) << (e * 8);
                lb4 |= ((uint32_t)(uint8_t)(int8_t)l) << (e * 8);
            }
            hw_[q] = hb4; lw_[q] = lb4;
        }
        uint32_t* dh = (uint32_t*)(g_zq + n * 128 + half * 32);
        uint32_t* dl = (uint32_t*)(g_zq + n * 128 + 64 + half * 32);
#pragma unroll
        for (int q = 0; q < 8; q++) { dh[q] = hw_[q]; dl[q] = lw_[q]; }
    }
}

// ---------------------------------------------------------------------------
// Main kernel: int8 IMMA 2-pass fixed-point GEMM + fused top-3 argmax.
// 256 CTAs x 256 threads (8 warps: 4 wm x 2 wn), 64 rows/CTA, 2 CTAs/SM.
// smem: A 8KB (transient) + 3 stages x 16KB = 56KB.
extern __shared__ char dsm[];
__global__ void __launch_bounds__(256, 2) imma_argmax_kernel() {
    uint32_t sraw = smem_u32(dsm);
    uint32_t dbase = (sraw + 1023) & ~1023u;
    char* dp = dsm + (int)(dbase - sraw);
    int tid = threadIdx.x, lane = tid & 31, wid = tid >> 5;
    int wm = wid & 3, wn = wid >> 2;
    int nbase = blockIdx.x * 64;

    // ---- A prologue: 64 rows x 128B of g_zq, swizzled ----
    {
        const int4* a4 = (const int4*)g_zq;
#pragma unroll
        for (int w = 0; w < 2; w++) {
            int i = tid + w * 256;           // 512 chunks
            int r = i >> 3, c = i & 7;
            cpa16(dbase + SW(r * 128 + c * 16), &a4[(nbase + r) * 8 + c]);
        }
        CP_COMMIT(); CP_WAIT0();
        __syncthreads();
    }

    // ---- A fragments (16 rows per warp, 4 k32-steps) ----
    uint32_t a[4][4];
    {
        int rA = ((lane >> 3) & 1) * 8 + (lane & 7);
        int kA = (lane >> 4) * 16;
#pragma unroll
        for (int ks = 0; ks < 4; ks++)
            ldsm4(a[ks], dbase + SW((uint32_t)((wm * 16 + rA) * 128 + ks * 32 + kA)));
    }
    __syncthreads();

    // ---- B ldmatrix offsets ----
    uint32_t offB[4][4];
    {
        int rB = ((lane >> 4) & 1) * 8 + (lane & 7);
        int kB = ((lane >> 3) & 1) * 16;
#pragma unroll
        for (int ks = 0; ks < 4; ks++)
#pragma unroll
            for (int p = 0; p < 4; p++)
                offB[ks][p] = SW((uint32_t)((wn * 64 + p * 16 + rB) * 128 + ks * 32 + kB));
    }

    // ---- prefetch setup (16KB/tile = 1024 chunks, 4/thread) ----
    uint32_t pf_s[4]; int pf_g[4];
#pragma unroll
    for (int w = 0; w < 4; w++) {
        int i = tid + w * 256;
        int r = i >> 3, c = i & 7;
        pf_s[w] = SW((uint32_t)(r * 128 + c * 16));
        pf_g[w] = r * 8 + c;
    }
    const int4* cq4 = (const int4*)g_cq;
    uint32_t bstage = dbase + 8192;
    auto prefetch = [&](int nt) {
        uint32_t st = bstage + (nt % 3) * 16384;
#pragma unroll
        for (int w = 0; w < 4; w++)
            cpa16(st + pf_s[w], &cq4[nt * 1024 + pf_g[w]]);
        CP_COMMIT();
    };
    prefetch(0); prefetch(1);

    // ---- per-row-slot top-3 state ----
    float v1[2], v2[2], v3[2];
    int i1[2], i2[2];
#pragma unroll
    for (int s = 0; s < 2; s++) { v1[s] = -3e18f; v2[s] = -3e18f; v3[s] = -3e18f; i1[s] = 0; i2[s] = 0; }

    for (int nt = 0; nt < NTILES; nt++) {
        if (nt < NTILES - 1) CP_WAIT1(); else CP_WAIT0();
        __syncthreads();
        if (nt < NTILES - 2) prefetch(nt + 2);
        uint32_t st = bstage + (nt % 3) * 16384;

        int C1[8][4], C2[8][4];
#pragma unroll
        for (int f = 0; f < 8; f++)
#pragma unroll
            for (int q = 0; q < 4; q++) { C1[f][q] = 0; C2[f][q] = 0; }

#pragma unroll
        for (int p = 0; p < 4; p++) {
            uint32_t b[4][4];
#pragma unroll
            for (int ks = 0; ks < 4; ks++) ldsm4(b[ks], st + offB[ks][p]);
            int f0 = 2 * p, f1 = 2 * p + 1;
            // pass 2: full k=128 ([hz|lz] . [lc|hc])
#pragma unroll
            for (int ks = 0; ks < 4; ks++) {
                mma_s8(C2[f0], a[ks], b[ks][0], b[ks][1]);
                mma_s8(C2[f1], a[ks], b[ks][2], b[ks][3]);
            }
            // pass 1: hh (A bytes 0-63 vs B bytes 64-127)
            mma_s8(C1[f0], a[0], b[2][0], b[2][1]);
            mma_s8(C1[f0], a[1], b[3][0], b[3][1]);
            mma_s8(C1[f1], a[0], b[2][2], b[2][3]);
            mma_s8(C1[f1], a[1], b[3][2], b[3][3]);
        }

        // ---- epilogue: combine + top-3 update ----
        int colq = (lane & 3) * 2;
#pragma unroll
        for (int s = 0; s < 2; s++) {
            float val[16];
#pragma unroll
            for (int f = 0; f < 8; f++) {
#pragma unroll
                for (int c = 0; c < 2; c++) {
                    int q = 2 * s + c;
                    val[f * 2 + c] = fmaf(65536.0f, (float)C1[f][q], 256.0f * (float)C2[f][q]);
                }
            }
            float tm = val[0];
#pragma unroll
            for (int e = 1; e < 16; e++) tm = fmaxf(tm, val[e]);
            if (tm > v3[s]) {
                int cb = nt * 128 + wn * 64;
#pragma unroll
                for (int e = 0; e < 16; e++) {
                    float v = val[e];
                    if (v > v3[s]) {
                        int f = e >> 1;
                        int col = cb + (f >> 1) * 16 + (f & 1) * 8 + colq + (e & 1);
                        if (v > v1[s]) { v3[s] = v2[s]; v2[s] = v1[s]; i2[s] = i1[s]; v1[s] = v; i1[s] = col; }
                        else if (v > v2[s]) { v3[s] = v2[s]; v2[s] = v; i2[s] = col; }
                        else v3[s] = v;
                    }
                }
            }
        }
    }

    // ---- quad merge (lane^1, lane^2 share rows) ----
#pragma unroll
    for (int s = 0; s < 2; s++) {
#pragma unroll
        for (int d = 1; d <= 2; d <<= 1) {
            float b1 = __shfl_xor_sync(0xFFFFFFFFu, v1[s], d);
            float b2 = __shfl_xor_sync(0xFFFFFFFFu, v2[s], d);
            float b3 = __shfl_xor_sync(0xFFFFFFFFu, v3[s], d);
            int  bi1 = __shfl_xor_sync(0xFFFFFFFFu, i1[s], d);
            int  bi2 = __shfl_xor_sync(0xFFFFFFFFu, i2[s], d);
            top3_merge(v1[s], i1[s], v2[s], i2[s], v3[s], b1, bi1, b2, bi2, b3);
        }
    }

    // ---- cross-wn merge via smem (A region is free now) ----
    __syncthreads();
    float* mv1 = (float*)dp;          // [2][64]
    float* mv2 = mv1 + 128;
    float* mv3 = mv2 + 128;
    int*   mi1 = (int*)(mv3 + 128);
    int*   mi2 = mi1 + 128;
    if ((lane & 3) == 0) {
#pragma unroll
        for (int s = 0; s < 2; s++) {
            int row = wm * 16 + s * 8 + (lane >> 2);
            int e = wn * 64 + row;
            mv1[e] = v1[s]; mv2[e] = v2[s]; mv3[e] = v3[s];
            mi1[e] = i1[s]; mi2[e] = i2[s];
        }
    }
    __syncthreads();
    if (tid < 64) {
        float a1 = mv1[tid], a2 = mv2[tid], a3 = mv3[tid];
        int   ai1 = mi1[tid], ai2 = mi2[tid];
        top3_merge(a1, ai1, a2, ai2, a3,
                   mv1[64 + tid], mi1[64 + tid], mv2[64 + tid], mi2[64 + tid], mv3[64 + tid]);
        int n = nbase + tid;
        g_idx[n] = ai1;
        if (a3 >= a1 - W_FIX) {
            int slot = atomicAdd(&g_nflagF, 1);
            g_flagF[slot] = n;
        } else if (a2 >= a1 - W_FIX) {
            int slot = atomicAdd(&g_nflag2, 1);
            g_f2n[slot] = n;
            g_f2j[slot] = ai2;
        }
    }
}

// ---------------------------------------------------------------------------
// Rescore: exact fp32 2-candidate picks + full rescans. warp per row.
__global__ void rescore_kernel(const float* __restrict__ z) {
    __shared__ float zrow[8][64];
    int wid = threadIdx.x >> 5, lane = threadIdx.x & 31;
    int gw = blockIdx.x * 8 + wid;
    const int NW = 64 * 8;

    // 2-candidate rows
    int n2 = g_nflag2;
    for (int f = gw; f < n2; f += NW) {
        int n = g_f2n[f], j2 = g_f2j[f];
        int j1 = g_idx[n];
        int b = n >> 10, hw = n & 1023;
        float zk0 = z[b * 65536 + lane * 1024 + hw];
        float zk1 = z[b * 65536 + (lane + 32) * 1024 + hw];
        float d1 = zk0 * g_cn[j1 * 64 + lane] + zk1 * g_cn[j1 * 64 + lane + 32];
        float d2 = zk0 * g_cn[j2 * 64 + lane] + zk1 * g_cn[j2 * 64 + lane + 32];
#pragma unroll
        for (int off = 16; off >= 1; off >>= 1) {
            d1 += __shfl_xor_sync(0xFFFFFFFFu, d1, off);
            d2 += __shfl_xor_sync(0xFFFFFFFFu, d2, off);
        }
        if (lane == 0 && (d2 > d1 || (d2 == d1 && j2 < j1))) g_idx[n] = j2;
    }

    // full-rescan rows
    int nf = g_nflagF;
    for (int f = gw; f < nf; f += NW) {
        int n = g_flagF[f];
        int b = n >> 10, hw = n & 1023;
        zrow[wid][lane]      = z[b * 65536 + lane * 1024 + hw];
        zrow[wid][lane + 32] = z[b * 65536 + (lane + 32) * 1024 + hw];
        __syncwarp();
        float v1 = -1e30f; int i1 = 0;
        for (int j = lane; j < K_CODES; j += 32) {
            const float4* cr = (const float4*)(g_cn + j * 64);
            float s = 0.0f;
#pragma unroll
            for (int q = 0; q < 16; q++) {
                float4 cv = cr[q];
                s += cv.x * zrow[wid][q * 4 + 0];
                s += cv.y * zrow[wid][q * 4 + 1];
                s += cv.z * zrow[wid][q * 4 + 2];
                s += cv.w * zrow[wid][q * 4 + 3];
            }
            if (s > v1) { v1 = s; i1 = j; }
        }
#pragma unroll
        for (int off = 16; off >= 1; off >>= 1) {
            float ov = __shfl_xor_sync(0xFFFFFFFFu, v1, off);
            int   oi = __shfl_xor_sync(0xFFFFFFFFu, i1, off);
            if (ov > v1 || (ov == v1 && oi < i1)) { v1 = ov; i1 = oi; }
        }
        if (lane == 0) g_idx[n] = i1;
        __syncwarp();
    }
}

// ---------------------------------------------------------------------------
// Gather + bincount + loss.
__global__ void gather_kernel(const float* __restrict__ z,
                              const float* __restrict__ embed,
                              float* __restrict__ out) {
    __shared__ float qt[64 * TSTR];
    int t = threadIdx.x;
    int nbase = blockIdx.x * 128;
    int b = nbase >> 10, hw0 = nbase & 1023;

    {
        int r = t >> 1, half = t & 1;
        int idx = g_idx[nbase + r];
        if (half == 0) atomicAdd(&g_bin[idx], 1);
        const float4* er = (const float4*)(embed + idx * 64 + half * 32);
#pragma unroll
        for (int q = 0; q < 8; q++) {
            float4 v = er[q];
            int k = half * 32 + q * 4;
            qt[(k + 0) * TSTR + r] = v.x;
            qt[(k + 1) * TSTR + r] = v.y;
            qt[(k + 2) * TSTR + r] = v.z;
            qt[(k + 3) * TSTR + r] = v.w;
        }
    }
    __syncthreads();

    float s = 0.0f;
#pragma unroll
    for (int i = 0; i < 8; i++) {
        int f4 = t + i * 256;
        int k = f4 >> 5, hw4 = (f4 & 31) * 4;
        float4 qv = *(float4*)&qt[k * TSTR + hw4];
        int off = b * 65536 + k * 1024 + hw0 + hw4;
        float4 zv = *(const float4*)&z[off];
        *(float4*)&out[off] = qv;
        float d0 = qv.x - zv.x, d1 = qv.y - zv.y, d2 = qv.z - zv.z, d3 = qv.w - zv.w;
        s += d0 * d0 + d1 * d1 + d2 * d2 + d3 * d3;
    }
#pragma unroll
    for (int off = 16; off >= 1; off >>= 1) s += __shfl_xor_sync(0xFFFFFFFFu, s, off);
    __shared__ float red[8];
    int lane = t & 31, wid = t >> 5;
    if (lane == 0) red[wid] = s;
    __syncthreads();
    if (wid == 0) {
        s = (lane < 8) ? red[lane] : 0.0f;
#pragma unroll
        for (int off = 4; off >= 1; off >>= 1) s += __shfl_xor_sync(0xFFFFFFFFu, s, off);
        if (lane == 0) atomicAdd(&g_lossd, (double)s);
    }
}

// ---------------------------------------------------------------------------
__global__ void finalize_kernel(float* __restrict__ out) {
    int t = blockIdx.x * blockDim.x + threadIdx.x;
    if (t == 0)
        out[OUT_ELEMS] = (float)(1.25 * g_lossd * (1.0 / (double)OUT_ELEMS));
    if (t < N_VEC)
        out[OUT_ELEMS + 1 + t] = (float)g_idx[t];
    if (t < K_CODES)
        out[OUT_ELEMS + 1 + N_VEC + t] = (float)g_bin[t];
}

// ---------------------------------------------------------------------------
extern "C" void kernel_launch(void* const* d_in, const int* in_sizes, int n_in,
                              void* d_out, int out_size) {
    const float* z     = (const float*)d_in[0];       // [16,64,32,32]
    const float* embed = (const float*)d_in[1];       // [8192,64]
    float* out = (float*)d_out;

    cudaFuncSetAttribute(imma_argmax_kernel,
                         cudaFuncAttributeMaxDynamicSharedMemorySize, 58368);

    prep_kernel<<<32 + 1024 + 128, 256>>>(z, embed);
    imma_argmax_kernel<<<256, 256, 58368>>>();
    rescore_kernel<<<64, 256>>>(z);
    gather_kernel<<<128, 256>>>(z, embed, out);
    finalize_kernel<<<96, 256>>>(out);
}

// round 10
// speedup vs baseline: 2.4625x; 2.1615x over previous
#include <cuda_runtime.h>
#include <cuda_fp16.h>
#include <math.h>
#include <stdint.h>

#define N_VEC   16384
#define K_CODES 8192
#define DDIM    64
#define OUT_ELEMS 1048576            // 16*64*32*32
#define NTILES  64                   // 8192 / 128
#define W_F     2e-3f

// ---------------------------------------------------------------------------
// scratch (no cudaMalloc allowed)
__device__ __align__(256) float  g_cn[K_CODES * DDIM];   // normalized codebook fp32
__device__ __align__(256) __half g_ch[K_CODES * DDIM];   // normalized codebook f16
__device__ __align__(256) __half g_zh[N_VEC * DDIM];     // z transposed [n][k] f16
__device__ int    g_idx[N_VEC];
__device__ int    g_bin[K_CODES];
__device__ int    g_flagF[N_VEC];     // full-rescan rows
__device__ int    g_f2n[N_VEC];       // 2-candidate rows
__device__ int    g_f2j[N_VEC];       // their 2nd candidate index
__device__ int    g_nflagF;
__device__ int    g_nflag2;
__device__ double g_lossd;

// ---------------------------------------------------------------------------
__device__ __forceinline__ uint32_t smem_u32(const void* p) {
    uint32_t a;
    asm("{ .reg .u64 t; cvta.to.shared.u64 t, %1; cvt.u32.u64 %0, t; }"
        : "=r"(a) : "l"(p));
    return a;
}
__device__ __forceinline__ void cpa16(uint32_t s, const void* g) {
    asm volatile("cp.async.cg.shared.global [%0], [%1], 16;" :: "r"(s), "l"(g));
}
#define CP_COMMIT() asm volatile("cp.async.commit_group;" ::: "memory")
#define CP_WAIT0()  asm volatile("cp.async.wait_group 0;" ::: "memory")
#define CP_WAIT1()  asm volatile("cp.async.wait_group 1;" ::: "memory")

__device__ __forceinline__ void ldsm4(uint32_t* r, uint32_t addr) {
    asm volatile("ldmatrix.sync.aligned.m8n8.x4.shared.b16 {%0,%1,%2,%3}, [%4];"
                 : "=r"(r[0]), "=r"(r[1]), "=r"(r[2]), "=r"(r[3]) : "r"(addr));
}
__device__ __forceinline__ void mma_f16(float* c, const uint32_t* a,
                                        uint32_t b0, uint32_t b1) {
    asm volatile("mma.sync.aligned.m16n8k16.row.col.f32.f16.f16.f32 "
                 "{%0,%1,%2,%3}, {%4,%5,%6,%7}, {%8,%9}, {%0,%1,%2,%3};"
                 : "+f"(c[0]), "+f"(c[1]), "+f"(c[2]), "+f"(c[3])
                 : "r"(a[0]), "r"(a[1]), "r"(a[2]), "r"(a[3]), "r"(b0), "r"(b1));
}
#define SW(x) ((x) ^ (((x) >> 3) & 0x70))
#define TSTR 132

// exact merge of two top-3 candidate sets (values + top-2 indices)
__device__ __forceinline__ void top3_merge(float& v1, int& i1, float& v2, int& i2,
                                           float& v3, float b1, int bi1, float b2,
                                           int bi2, float b3) {
    bool bw = (b1 > v1) || (b1 == v1 && bi1 < i1);
    float x, y2, c2v, c3; int xi, c2i;
    if (bw) { x = v1; xi = i1; y2 = v2; c2v = b2; c2i = bi2; c3 = b3; v1 = b1; i1 = bi1; }
    else    { x = b1; xi = bi1; y2 = b2; c2v = v2; c2i = i2; c3 = v3; }
    if (x > c2v || (x == c2v && xi < c2i)) { v2 = x; i2 = xi; v3 = fmaxf(y2, c2v); }
    else                                   { v2 = c2v; i2 = c2i; v3 = fmaxf(x, c3); }
}

// ---------------------------------------------------------------------------
// Fused prep: zero counters | normalize codebook -> fp32+f16 | transpose z -> f16
__global__ void prep_kernel(const float* __restrict__ z,
                            const float* __restrict__ embed) {
    int blk = blockIdx.x;
    int t = threadIdx.x;
    if (blk < 32) {
        int i = blk * 256 + t;
        if (i < K_CODES) g_bin[i] = 0;
        if (i == 0) { g_lossd = 0.0; g_nflagF = 0; g_nflag2 = 0; }
    } else if (blk < 32 + 1024) {
        // ---- codebook: normalize -> fp32 + f16 ----
        int wid = t >> 5, lane = t & 31;
        int row = (blk - 32) * 8 + wid;
        float a = embed[row * 64 + lane];
        float b = embed[row * 64 + lane + 32];
        float s = a * a + b * b;
#pragma unroll
        for (int off = 16; off >= 1; off >>= 1) s += __shfl_xor_sync(0xFFFFFFFFu, s, off);
        float inv = 1.0f / fmaxf(sqrtf(s), 1e-12f);
        float ca = a * inv, cb = b * inv;
        g_cn[row * 64 + lane] = ca;
        g_cn[row * 64 + lane + 32] = cb;
        g_ch[row * 64 + lane]      = __float2half_rn(ca);
        g_ch[row * 64 + lane + 32] = __float2half_rn(cb);
    } else {
        // ---- z: transpose -> f16 [n][k] ----
        __shared__ float tile[64 * TSTR];
        int bb = blk - (32 + 1024);
        int b = bb >> 3;
        int hwb = bb & 7;
        const float4* z4 = (const float4*)z;
#pragma unroll
        for (int i = 0; i < 8; i++) {
            int f4 = t + i * 256;
            int k = f4 >> 5, w = f4 & 31;
            *(float4*)&tile[k * TSTR + w * 4] = z4[b * 16384 + k * 256 + hwb * 32 + w];
        }
        __syncthreads();
        int r = t >> 1, half = t & 1;
        int n = b * 1024 + hwb * 128 + r;
        __half2* zh2 = (__half2*)g_zh;
#pragma unroll
        for (int kk = 0; kk < 16; kk++) {
            int k = half * 32 + kk * 2;
            float v0 = tile[k * TSTR + r];
            float v1 = tile[(k + 1) * TSTR + r];
            zh2[(n * 64 + k) >> 1] = __floats2half2_rn(v0, v1);
        }
    }
}

// ---------------------------------------------------------------------------
// Main kernel: single-pass f16 HMMA GEMM + fused top-3 argmax.
// 256 CTAs x 256 threads (8 warps: 4 wm x 2 wn), 64 rows/CTA, 2 CTAs/SM.
// smem: A 8KB (transient) + 3 stages x 16KB = 56KB.
extern __shared__ char dsm[];
__global__ void __launch_bounds__(256, 2) hmma_argmax_kernel() {
    uint32_t sraw = smem_u32(dsm);
    uint32_t dbase = (sraw + 1023) & ~1023u;
    char* dp = dsm + (int)(dbase - sraw);
    int tid = threadIdx.x, lane = tid & 31, wid = tid >> 5;
    int wm = wid & 3, wn = wid >> 2;
    int nbase = blockIdx.x * 64;

    // ---- A prologue: 64 rows x 128B of g_zh, swizzled ----
    {
        const int4* a4 = (const int4*)g_zh;
#pragma unroll
        for (int w = 0; w < 2; w++) {
            int i = tid + w * 256;           // 512 chunks
            int r = i >> 3, c = i & 7;
            cpa16(dbase + SW(r * 128 + c * 16), &a4[(nbase + r) * 8 + c]);
        }
        CP_COMMIT(); CP_WAIT0();
        __syncthreads();
    }

    // ---- A fragments (16 rows per warp, 4 k16-steps) ----
    uint32_t a[4][4];
    {
        int rA = ((lane >> 3) & 1) * 8 + (lane & 7);
        int kA = (lane >> 4) * 16;
#pragma unroll
        for (int ks = 0; ks < 4; ks++)
            ldsm4(a[ks], dbase + SW((uint32_t)((wm * 16 + rA) * 128 + ks * 32 + kA)));
    }
    __syncthreads();

    // ---- B ldmatrix offsets ----
    uint32_t offB[4][4];
    {
        int rB = ((lane >> 4) & 1) * 8 + (lane & 7);
        int kB = ((lane >> 3) & 1) * 16;
#pragma unroll
        for (int ks = 0; ks < 4; ks++)
#pragma unroll
            for (int p = 0; p < 4; p++)
                offB[ks][p] = SW((uint32_t)((wn * 64 + p * 16 + rB) * 128 + ks * 32 + kB));
    }

    // ---- prefetch setup (16KB/tile = 1024 chunks, 4/thread) ----
    uint32_t pf_s[4]; int pf_g[4];
#pragma unroll
    for (int w = 0; w < 4; w++) {
        int i = tid + w * 256;
        int r = i >> 3, c = i & 7;
        pf_s[w] = SW((uint32_t)(r * 128 + c * 16));
        pf_g[w] = r * 8 + c;
    }
    const int4* ch4 = (const int4*)g_ch;
    uint32_t bstage = dbase + 8192;
    auto prefetch = [&](int nt) {
        uint32_t st = bstage + (nt % 3) * 16384;
#pragma unroll
        for (int w = 0; w < 4; w++)
            cpa16(st + pf_s[w], &ch4[nt * 1024 + pf_g[w]]);
        CP_COMMIT();
    };
    prefetch(0); prefetch(1);

    // ---- per-row-slot top-3 state ----
    float v1[2], v2[2], v3[2];
    int i1[2], i2[2];
#pragma unroll
    for (int s = 0; s < 2; s++) { v1[s] = -1e30f; v2[s] = -1e30f; v3[s] = -1e30f; i1[s] = 0; i2[s] = 0; }

    for (int nt = 0; nt < NTILES; nt++) {
        if (nt < NTILES - 1) CP_WAIT1(); else CP_WAIT0();
        __syncthreads();
        if (nt < NTILES - 2) prefetch(nt + 2);
        uint32_t st = bstage + (nt % 3) * 16384;

        float C[8][4];
#pragma unroll
        for (int f = 0; f < 8; f++)
#pragma unroll
            for (int q = 0; q < 4; q++) C[f][q] = 0.0f;

#pragma unroll
        for (int p = 0; p < 4; p++) {
            uint32_t b[4][4];
#pragma unroll
            for (int ks = 0; ks < 4; ks++) ldsm4(b[ks], st + offB[ks][p]);
            int f0 = 2 * p, f1 = 2 * p + 1;
#pragma unroll
            for (int ks = 0; ks < 4; ks++) {
                mma_f16(C[f0], a[ks], b[ks][0], b[ks][1]);
                mma_f16(C[f1], a[ks], b[ks][2], b[ks][3]);
            }
        }

        // ---- top-3 update (2 row slots x 16 values) ----
        int colq = (lane & 3) * 2;
#pragma unroll
        for (int s = 0; s < 2; s++) {
            float tm = C[0][2 * s];
#pragma unroll
            for (int f = 0; f < 8; f++) {
                tm = fmaxf(tm, C[f][2 * s]);
                tm = fmaxf(tm, C[f][2 * s + 1]);
            }
            if (tm > v3[s]) {
                int cb = nt * 128 + wn * 64;
#pragma unroll
                for (int f = 0; f < 8; f++) {
#pragma unroll
                    for (int c = 0; c < 2; c++) {
                        float v = C[f][2 * s + c];
                        if (v > v3[s]) {
                            int col = cb + (f >> 1) * 16 + (f & 1) * 8 + colq + c;
                            if (v > v1[s]) { v3[s] = v2[s]; v2[s] = v1[s]; i2[s] = i1[s]; v1[s] = v; i1[s] = col; }
                            else if (v > v2[s]) { v3[s] = v2[s]; v2[s] = v; i2[s] = col; }
                            else v3[s] = v;
                        }
                    }
                }
            }
        }
    }

    // ---- quad merge (lane^1, lane^2 share rows) ----
#pragma unroll
    for (int s = 0; s < 2; s++) {
#pragma unroll
        for (int d = 1; d <= 2; d <<= 1) {
            float b1 = __shfl_xor_sync(0xFFFFFFFFu, v1[s], d);
            float b2 = __shfl_xor_sync(0xFFFFFFFFu, v2[s], d);
            float b3 = __shfl_xor_sync(0xFFFFFFFFu, v3[s], d);
            int  bi1 = __shfl_xor_sync(0xFFFFFFFFu, i1[s], d);
            int  bi2 = __shfl_xor_sync(0xFFFFFFFFu, i2[s], d);
            top3_merge(v1[s], i1[s], v2[s], i2[s], v3[s], b1, bi1, b2, bi2, b3);
        }
    }

    // ---- cross-wn merge via smem (A region is free now) ----
    __syncthreads();
    float* mv1 = (float*)dp;          // [2][64]
    float* mv2 = mv1 + 128;
    float* mv3 = mv2 + 128;
    int*   mi1 = (int*)(mv3 + 128);
    int*   mi2 = mi1 + 128;
    if ((lane & 3) == 0) {
#pragma unroll
        for (int s = 0; s < 2; s++) {
            int row = wm * 16 + s * 8 + (lane >> 2);
            int e = wn * 64 + row;
            mv1[e] = v1[s]; mv2[e] = v2[s]; mv3[e] = v3[s];
            mi1[e] = i1[s]; mi2[e] = i2[s];
        }
    }
    __syncthreads();
    if (tid < 64) {
        float a1 = mv1[tid], a2 = mv2[tid], a3 = mv3[tid];
        int   ai1 = mi1[tid], ai2 = mi2[tid];
        top3_merge(a1, ai1, a2, ai2, a3,
                   mv1[64 + tid], mi1[64 + tid], mv2[64 + tid], mi2[64 + tid], mv3[64 + tid]);
        int n = nbase + tid;
        g_idx[n] = ai1;
        if (a3 >= a1 - W_F) {
            int slot = atomicAdd(&g_nflagF, 1);
            g_flagF[slot] = n;
        } else if (a2 >= a1 - W_F) {
            int slot = atomicAdd(&g_nflag2, 1);
            g_f2n[slot] = n;
            g_f2j[slot] = ai2;
        }
    }
}

// ---------------------------------------------------------------------------
// Rescore: exact fp32 2-candidate picks + full rescans. warp per row.
__global__ void rescore_kernel(const float* __restrict__ z) {
    __shared__ float zrow[8][64];
    int wid = threadIdx.x >> 5, lane = threadIdx.x & 31;
    int gw = blockIdx.x * 8 + wid;
    const int NW = 64 * 8;

    // 2-candidate rows
    int n2 = g_nflag2;
    for (int f = gw; f < n2; f += NW) {
        int n = g_f2n[f], j2 = g_f2j[f];
        int j1 = g_idx[n];
        int b = n >> 10, hw = n & 1023;
        float zk0 = z[b * 65536 + lane * 1024 + hw];
        float zk1 = z[b * 65536 + (lane + 32) * 1024 + hw];
        float d1 = zk0 * g_cn[j1 * 64 + lane] + zk1 * g_cn[j1 * 64 + lane + 32];
        float d2 = zk0 * g_cn[j2 * 64 + lane] + zk1 * g_cn[j2 * 64 + lane + 32];
#pragma unroll
        for (int off = 16; off >= 1; off >>= 1) {
            d1 += __shfl_xor_sync(0xFFFFFFFFu, d1, off);
            d2 += __shfl_xor_sync(0xFFFFFFFFu, d2, off);
        }
        if (lane == 0 && (d2 > d1 || (d2 == d1 && j2 < j1))) g_idx[n] = j2;
    }

    // full-rescan rows
    int nf = g_nflagF;
    for (int f = gw; f < nf; f += NW) {
        int n = g_flagF[f];
        int b = n >> 10, hw = n & 1023;
        zrow[wid][lane]      = z[b * 65536 + lane * 1024 + hw];
        zrow[wid][lane + 32] = z[b * 65536 + (lane + 32) * 1024 + hw];
        __syncwarp();
        float v1 = -1e30f; int i1 = 0;
        for (int j = lane; j < K_CODES; j += 32) {
            const float4* cr = (const float4*)(g_cn + j * 64);
            float s = 0.0f;
#pragma unroll
            for (int q = 0; q < 16; q++) {
                float4 cv = cr[q];
                s += cv.x * zrow[wid][q * 4 + 0];
                s += cv.y * zrow[wid][q * 4 + 1];
                s += cv.z * zrow[wid][q * 4 + 2];
                s += cv.w * zrow[wid][q * 4 + 3];
            }
            if (s > v1) { v1 = s; i1 = j; }
        }
#pragma unroll
        for (int off = 16; off >= 1; off >>= 1) {
            float ov = __shfl_xor_sync(0xFFFFFFFFu, v1, off);
            int   oi = __shfl_xor_sync(0xFFFFFFFFu, i1, off);
            if (ov > v1 || (ov == v1 && oi < i1)) { v1 = ov; i1 = oi; }
        }
        if (lane == 0) g_idx[n] = i1;
        __syncwarp();
    }
}

// ---------------------------------------------------------------------------
// Gather + bincount + loss.
__global__ void gather_kernel(const float* __restrict__ z,
                              const float* __restrict__ embed,
                              float* __restrict__ out) {
    __shared__ float qt[64 * TSTR];
    int t = threadIdx.x;
    int nbase = blockIdx.x * 128;
    int b = nbase >> 10, hw0 = nbase & 1023;

    {
        int r = t >> 1, half = t & 1;
        int idx = g_idx[nbase + r];
        if (half == 0) atomicAdd(&g_bin[idx], 1);
        const float4* er = (const float4*)(embed + idx * 64 + half * 32);
#pragma unroll
        for (int q = 0; q < 8; q++) {
            float4 v = er[q];
            int k = half * 32 + q * 4;
            qt[(k + 0) * TSTR + r] = v.x;
            qt[(k + 1) * TSTR + r] = v.y;
            qt[(k + 2) * TSTR + r] = v.z;
            qt[(k + 3) * TSTR + r] = v.w;
        }
    }
    __syncthreads();

    float s = 0.0f;
#pragma unroll
    for (int i = 0; i < 8; i++) {
        int f4 = t + i * 256;
        int k = f4 >> 5, hw4 = (f4 & 31) * 4;
        float4 qv = *(float4*)&qt[k * TSTR + hw4];
        int off = b * 65536 + k * 1024 + hw0 + hw4;
        float4 zv = *(const float4*)&z[off];
        *(float4*)&out[off] = qv;
        float d0 = qv.x - zv.x, d1 = qv.y - zv.y, d2 = qv.z - zv.z, d3 = qv.w - zv.w;
        s += d0 * d0 + d1 * d1 + d2 * d2 + d3 * d3;
    }
#pragma unroll
    for (int off = 16; off >= 1; off >>= 1) s += __shfl_xor_sync(0xFFFFFFFFu, s, off);
    __shared__ float red[8];
    int lane = t & 31, wid = t >> 5;
    if (lane == 0) red[wid] = s;
    __syncthreads();
    if (wid == 0) {
        s = (lane < 8) ? red[lane] : 0.0f;
#pragma unroll
        for (int off = 4; off >= 1; off >>= 1) s += __shfl_xor_sync(0xFFFFFFFFu, s, off);
        if (lane == 0) atomicAdd(&g_lossd, (double)s);
    }
}

// ---------------------------------------------------------------------------
__global__ void finalize_kernel(float* __restrict__ out) {
    int t = blockIdx.x * blockDim.x + threadIdx.x;
    if (t == 0)
        out[OUT_ELEMS] = (float)(1.25 * g_lossd * (1.0 / (double)OUT_ELEMS));
    if (t < N_VEC)
        out[OUT_ELEMS + 1 + t] = (float)g_idx[t];
    if (t < K_CODES)
        out[OUT_ELEMS + 1 + N_VEC + t] = (float)g_bin[t];
}

// ---------------------------------------------------------------------------
extern "C" void kernel_launch(void* const* d_in, const int* in_sizes, int n_in,
                              void* d_out, int out_size) {
    const float* z     = (const float*)d_in[0];       // [16,64,32,32]
    const float* embed = (const float*)d_in[1];       // [8192,64]
    float* out = (float*)d_out;

    cudaFuncSetAttribute(hmma_argmax_kernel,
                         cudaFuncAttributeMaxDynamicSharedMemorySize, 58368);

    prep_kernel<<<32 + 1024 + 128, 256>>>(z, embed);
    hmma_argmax_kernel<<<256, 256, 58368>>>();
    rescore_kernel<<<64, 256>>>(z);
    gather_kernel<<<128, 256>>>(z, embed, out);
    finalize_kernel<<<96, 256>>>(out);
}